// round 10
// baseline (speedup 1.0000x reference)
#include <cuda_runtime.h>
#include <cstdint>

// ============================================================================
// DistNet: out[n] = sigmoid((max(0, ||x||^2 + min_p(||p||^2 - 2 x.p)) + alpha)/beta)
// R10: INT8 IMMA (mma.sync m16n8k32 s8.s8.s32) on the proven R7 two-stage
// pair-private pipeline. Quantization scale S=20 fixed; norms exact f32;
// min folded in f32 from s32 accumulators. Halves tensor instructions,
// LDSM ops, and B smem/L2 traffic vs fp16 k16.
// ============================================================================

static constexpr int NROWS  = 65536;
static constexpr int DIM    = 128;   // 128 bytes/row in s8
static constexpr int NPTS   = 2048;
static constexpr int MTILE  = 64;
static constexpr int SUBPTS = 32;            // points per sub-chunk
static constexpr int NSUB   = 512 / SUBPTS;  // 16 sub-chunks per pair

#define LOG1000F 6.9077542789816375f
#define QS       20.0f                       // quantization scale
#define NINV     (-2.0f / (QS * QS))         // -2/S^2

__device__ __align__(16) char  g_pts[NPTS * DIM];  // s8 points, K-major
__device__ __align__(16) float g_pn[NPTS];         // ||p||^2 exact f32

// smem layout (dynamic)
static constexpr int OFF_X    = 0;        // 8192: X tile (64 x 128B s8)
static constexpr int OFF_B    = 8192;     // 32768: 4 pairs x 2 x 4KB stages
static constexpr int OFF_PN   = 40960;    // 8192: ||p||^2 f32, 2KB per pair
static constexpr int OFF_XN   = 49152;    // 256: ||x||^2 per row
static constexpr int OFF_MIN  = 49408;    // 768: min-combine
static constexpr int SMEM_BYTES = 50304;

static constexpr int BUFBYTES = SUBPTS * DIM;   // 4096 per stage buffer

// ---------------------------------------------------------------------------
__device__ __forceinline__ uint32_t smem_u32(const void* p) {
    uint32_t a;
    asm("{ .reg .u64 t; cvta.to.shared.u64 t, %1; cvt.u32.u64 %0, t; }"
        : "=r"(a) : "l"(p));
    return a;
}

__device__ __forceinline__ void cp_async16(uint32_t dst, const void* src) {
    asm volatile("cp.async.cg.shared.global [%0], [%1], 16;"
                 :: "r"(dst), "l"(src) : "memory");
}

#define LDMATRIX_X4(R, ADDR)                                                   \
    asm volatile("ldmatrix.sync.aligned.m8n8.x4.shared.b16 {%0,%1,%2,%3}, [%4];" \
                 : "=r"((R)[0]), "=r"((R)[1]), "=r"((R)[2]), "=r"((R)[3])       \
                 : "r"(ADDR))

// s8 IMMA, k=32, s32 accumulators
#define MMA16832I(C, A, B0, B1)                                                \
    asm volatile("mma.sync.aligned.m16n8k32.row.col.s32.s8.s8.s32 "            \
                 "{%0,%1,%2,%3}, {%4,%5,%6,%7}, {%8,%9}, {%0,%1,%2,%3};"       \
                 : "+r"((C)[0]), "+r"((C)[1]), "+r"((C)[2]), "+r"((C)[3])      \
                 : "r"((A)[0]), "r"((A)[1]), "r"((A)[2]), "r"((A)[3]),         \
                   "r"(B0), "r"(B1))

__device__ __forceinline__ int q8(float v) {
    int i = __float2int_rn(v * QS);
    return max(-127, min(127, i));
}

// ---------------------------------------------------------------------------
// Prep: points f32 -> s8 row-major + exact ||p||^2 (f32)
__global__ void distnet_prep(const float* __restrict__ pts) {
    int p = blockIdx.x;
    int t = threadIdx.x;  // 128 = DIM
    float v = pts[p * DIM + t];
    g_pts[p * DIM + t] = (char)q8(v);
    float s = v * v;
#pragma unroll
    for (int o = 16; o > 0; o >>= 1) s += __shfl_xor_sync(0xffffffffu, s, o);
    __shared__ float ws[4];
    if ((t & 31) == 0) ws[t >> 5] = s;
    __syncthreads();
    if (t == 0) g_pn[p] = ws[0] + ws[1] + ws[2] + ws[3];
}

// ---------------------------------------------------------------------------
// Pair-scope async copy of one 32-point sub-chunk (4KB). tp in [0,64).
// Swizzle: 16B unit c (0..7) of point row n -> n*128 + ((c ^ (n&7))*16).
__device__ __forceinline__ void issue_sub(uint32_t dst, int pair, int sub, int tp) {
    const char* src = g_pts + ((size_t)pair * 512 + sub * SUBPTS) * DIM;
#pragma unroll
    for (int u = 0; u < 4; u++) {
        int i = tp + u * 64;             // 0..255 16B units
        int n = i >> 3, c = i & 7;
        cp_async16(dst + n * 128 + ((c ^ (n & 7)) * 16), src + i * 16);
    }
    asm volatile("cp.async.commit_group;" ::: "memory");
}

// ---------------------------------------------------------------------------
__global__ void __launch_bounds__(256, 2)
distnet_main(const float* __restrict__ x, const float* __restrict__ beta_raw,
             float* __restrict__ out) {
    extern __shared__ char smem[];
    const uint32_t sb = smem_u32(smem);
    const int tid   = threadIdx.x;
    const int lane  = tid & 31;
    const int wid   = tid >> 5;        // 0..7
    const int mhalf = wid & 1;         // m32 half of the 64-row tile
    const int pair  = wid >> 1;        // 0..3, owns points [512*pair, +512)
    const int tp    = tid & 63;        // thread index within pair
    const int row0  = blockIdx.x * MTILE;

    const uint32_t buf0 = sb + OFF_B + pair * (2 * BUFBYTES);
    const uint32_t buf1 = buf0 + BUFBYTES;

    // prologue: pn (2KB f32) + sub-chunk 0, one commit group
    {
        const char* pns = (const char*)(g_pn + pair * 512);
        cp_async16(sb + OFF_PN + pair * 2048 + tp * 16, pns + tp * 16);
        cp_async16(sb + OFF_PN + pair * 2048 + 1024 + tp * 16, pns + 1024 + tp * 16);
    }
    issue_sub(buf0, pair, 0, tp);

    // ---- X tile: 64 rows x 128B s8, 4 threads per row + exact ||x||^2
    {
        int sub = tid & 3;             // owns dims [32*sub, +32) = units 2sub..2sub+1
        int r   = tid >> 2;            // 0..63
        const float4* src = (const float4*)(x + (size_t)(row0 + r) * DIM) + sub * 8;
        float s = 0.f;
#pragma unroll
        for (int u = 0; u < 2; u++) {  // two 16B output units
            uint32_t w[4];
#pragma unroll
            for (int j = 0; j < 4; j++) {
                float4 v = src[u * 4 + j];
                s += v.x * v.x + v.y * v.y + v.z * v.z + v.w * v.w;
                w[j] = (uint32_t)(q8(v.x) & 255) | ((uint32_t)(q8(v.y) & 255) << 8) |
                       ((uint32_t)(q8(v.z) & 255) << 16) | ((uint32_t)(q8(v.w) & 255) << 24);
            }
            uint4 pk = make_uint4(w[0], w[1], w[2], w[3]);
            int c = sub * 2 + u;
            *(uint4*)(smem + OFF_X + r * 128 + ((c ^ (r & 7)) * 16)) = pk;
        }
        s += __shfl_xor_sync(0xffffffffu, s, 1);
        s += __shfl_xor_sync(0xffffffffu, s, 2);
        if (sub == 0) ((float*)(smem + OFF_XN))[r] = s;
    }
    __syncthreads();

    // ---- A fragments: warp owns rows mhalf*32..+31; 4 k32-steps, load once
    uint32_t afr[2][4][4];
    {
        int ar = lane & 15, ah = lane >> 4;   // row-in-tile, 16B-half of k32 step
#pragma unroll
        for (int mt = 0; mt < 2; mt++) {
            int r = mhalf * 32 + mt * 16 + ar;
#pragma unroll
            for (int ks = 0; ks < 4; ks++) {
                uint32_t addr = sb + OFF_X + r * 128 + (((2 * ks + ah) ^ (r & 7)) * 16);
                LDMATRIX_X4(afr[mt][ks], addr);
            }
        }
    }

    const int q  = lane & 3;   // col pair within n8
    const int rp = lane >> 2;  // row within 8
    const uint32_t br_ = lane & 7, bh = lane >> 3;  // B ldmatrix lane mapping
    const int barid = pair + 1;
    const float* pnp = (const float*)(smem + OFF_PN + pair * 2048);

    float rmin[4] = {3.4e38f, 3.4e38f, 3.4e38f, 3.4e38f};

    // ---- mainloop: two-stage pair-private pipeline (R7 scheme)
#pragma unroll 1
    for (int i = 0; i < NSUB; i++) {
        uint32_t buf = (i & 1) ? buf1 : buf0;
        asm volatile("cp.async.wait_group 0;" ::: "memory");
        asm volatile("bar.sync %0, 64;" :: "r"(barid) : "memory");
        if (i + 1 < NSUB)
            issue_sub((i & 1) ? buf0 : buf1, pair, i + 1, tp);

        const float* pnb = pnp + i * SUBPTS;
        const uint32_t bl = buf + br_ * 128;
#pragma unroll
        for (int g = 0; g < 4; g++) {   // 4 n8-groups of this sub-chunk
            // 2 x4-ldmatrix cover k128 for this n8 group
            uint32_t bfr[2][4];
#pragma unroll
            for (int kk = 0; kk < 2; kk++) {
                uint32_t addr = bl + g * 1024 + (((4 * kk + bh) ^ br_) * 16);
                LDMATRIX_X4(bfr[kk], addr);
            }
            int a0[4] = {0, 0, 0, 0}, a1[4] = {0, 0, 0, 0};
            MMA16832I(a0, afr[0][0], bfr[0][0], bfr[0][1]);
            MMA16832I(a1, afr[1][0], bfr[0][0], bfr[0][1]);
            MMA16832I(a0, afr[0][1], bfr[0][2], bfr[0][3]);
            MMA16832I(a1, afr[1][1], bfr[0][2], bfr[0][3]);
            MMA16832I(a0, afr[0][2], bfr[1][0], bfr[1][1]);
            MMA16832I(a1, afr[1][2], bfr[1][0], bfr[1][1]);
            MMA16832I(a0, afr[0][3], bfr[1][2], bfr[1][3]);
            MMA16832I(a1, afr[1][3], bfr[1][2], bfr[1][3]);

            float2 pp = *(const float2*)(pnb + g * 8 + 2 * q);
            rmin[0] = fminf(rmin[0], fminf(__fmaf_rn(NINV, (float)a0[0], pp.x),
                                           __fmaf_rn(NINV, (float)a0[1], pp.y)));
            rmin[1] = fminf(rmin[1], fminf(__fmaf_rn(NINV, (float)a0[2], pp.x),
                                           __fmaf_rn(NINV, (float)a0[3], pp.y)));
            rmin[2] = fminf(rmin[2], fminf(__fmaf_rn(NINV, (float)a1[0], pp.x),
                                           __fmaf_rn(NINV, (float)a1[1], pp.y)));
            rmin[3] = fminf(rmin[3], fminf(__fmaf_rn(NINV, (float)a1[2], pp.x),
                                           __fmaf_rn(NINV, (float)a1[3], pp.y)));
        }
    }

    // ---- reduce across the quad (cols) within each warp
#pragma unroll
    for (int i = 0; i < 4; i++) {
        rmin[i] = fminf(rmin[i], __shfl_xor_sync(0xffffffffu, rmin[i], 1));
        rmin[i] = fminf(rmin[i], __shfl_xor_sync(0xffffffffu, rmin[i], 2));
    }
    // rmin[i] -> row mhalf*32 + i*8 + rp (i in 0..3 covers rp, +8, +16, +24)

    // ---- combine the four pairs via smem, then epilogue
    float* minbuf = (float*)(smem + OFF_MIN);   // [3][64]
    if (pair > 0 && q == 0) {
#pragma unroll
        for (int i = 0; i < 4; i++)
            minbuf[(pair - 1) * 64 + mhalf * 32 + ((i < 2) ? i * 8 : (i - 2) * 8 + 16) + rp]
                = rmin[i];
    }
    __syncthreads();
    if (pair == 0 && q == 0) {
        const float* xn_s = (const float*)(smem + OFF_XN);
        float brv  = beta_raw[0];
        float beta = fmaxf(brv, 0.f) + log1pf(__expf(-fabsf(brv)));  // softplus
#pragma unroll
        for (int i = 0; i < 4; i++) {
            int rl = mhalf * 32 + ((i < 2) ? i * 8 : (i - 2) * 8 + 16) + rp;
            float mn = rmin[i];
            mn = fminf(mn, minbuf[rl]);
            mn = fminf(mn, minbuf[64 + rl]);
            mn = fminf(mn, minbuf[128 + rl]);
            float md  = fmaxf(xn_s[rl] + mn, 0.f);
            float arg = (md - beta * LOG1000F) / beta;
            out[row0 + rl] = 1.f / (1.f + __expf(-arg));
        }
    }
}

// ---------------------------------------------------------------------------
extern "C" void kernel_launch(void* const* d_in, const int* in_sizes, int n_in,
                              void* d_out, int out_size) {
    const float* x    = (const float*)d_in[0];   // [65536,128]
    const float* pts  = (const float*)d_in[1];   // [2048,128]
    const float* braw = (const float*)d_in[2];   // [1]
    float* out = (float*)d_out;                  // [65536]

    cudaFuncSetAttribute(distnet_main, cudaFuncAttributeMaxDynamicSharedMemorySize,
                         SMEM_BYTES);

    distnet_prep<<<NPTS, DIM>>>(pts);
    distnet_main<<<NROWS / MTILE, 256, SMEM_BYTES>>>(x, braw, out);
}

// round 11
// speedup vs baseline: 2.6527x; 2.6527x over previous
#include <cuda_runtime.h>
#include <cuda_fp16.h>
#include <cstdint>

// ============================================================================
// DistNet: out[n] = sigmoid((max(0, ||x||^2 + min_p(||p||^2 - 2 x.p)) + alpha)/beta)
// R11: R7 fp16 HMMA core, but each 64-row tile is split across 2 CTAs
// (1024 points each) -> grid 2048, T_CTA halved, wave-tail loss halved.
// Partial row-mins combined via atomicMin on order-preserving uint keys;
// final sigmoid in a tiny epilogue kernel.
// ============================================================================

static constexpr int NROWS  = 65536;
static constexpr int DIM    = 128;
static constexpr int NPTS   = 2048;
static constexpr int MTILE  = 64;
static constexpr int SUBPTS = 32;            // points per sub-chunk
static constexpr int NSUB   = 256 / SUBPTS;  // 8 sub-chunks per pair (256 pts)

#define LOG1000F 6.9077542789816375f

__device__ __align__(16) __half g_pts[NPTS * DIM];  // fp16 points, K-major
__device__ __align__(16) __half g_pn[NPTS];         // ||p||^2 (fp16)
__device__ unsigned g_min[NROWS];                   // order-preserving uint keys
__device__ float    g_xn[NROWS];                    // ||x||^2 per row

// smem layout (dynamic)
static constexpr int OFF_X     = 0;                    // 64 x 256B = 16384
static constexpr int OFF_B     = 16384;
static constexpr int BUFBYTES  = SUBPTS * 256;         // 8192 per stage buffer
static constexpr int BUFSTRIDE = BUFBYTES + 128;       // + pn (64B) + pad
static constexpr int PAIRBYTES = 2 * BUFSTRIDE;
static constexpr int SMEM_BYTES = OFF_B + 4 * PAIRBYTES + 128;  // ~83200 -> occ 2

// ---------------------------------------------------------------------------
__device__ __forceinline__ uint32_t smem_u32(const void* p) {
    uint32_t a;
    asm("{ .reg .u64 t; cvta.to.shared.u64 t, %1; cvt.u32.u64 %0, t; }"
        : "=r"(a) : "l"(p));
    return a;
}

__device__ __forceinline__ void cp_async16(uint32_t dst, const void* src) {
    asm volatile("cp.async.cg.shared.global [%0], [%1], 16;"
                 :: "r"(dst), "l"(src) : "memory");
}

#define LDMATRIX_X4(R, ADDR)                                                   \
    asm volatile("ldmatrix.sync.aligned.m8n8.x4.shared.b16 {%0,%1,%2,%3}, [%4];" \
                 : "=r"((R)[0]), "=r"((R)[1]), "=r"((R)[2]), "=r"((R)[3])       \
                 : "r"(ADDR))

#define MMA16816H(C, A, B0, B1)                                                \
    asm volatile("mma.sync.aligned.m16n8k16.row.col.f16.f16.f16.f16 "          \
                 "{%0,%1}, {%2,%3,%4,%5}, {%6,%7}, {%0,%1};"                   \
                 : "+r"((C)[0]), "+r"((C)[1])                                  \
                 : "r"((A)[0]), "r"((A)[1]), "r"((A)[2]), "r"((A)[3]),         \
                   "r"(B0), "r"(B1))

// order-preserving float->uint key (monotone: smaller float -> smaller key)
__device__ __forceinline__ unsigned fkey(float f) {
    unsigned b = __float_as_uint(f);
    return (b & 0x80000000u) ? ~b : (b | 0x80000000u);
}
__device__ __forceinline__ float funkey(unsigned k) {
    return __uint_as_float((k & 0x80000000u) ? (k ^ 0x80000000u) : ~k);
}

// ---------------------------------------------------------------------------
// Prep: points f32 -> fp16 row-major + ||p||^2 (fp16)
__global__ void distnet_prep(const float* __restrict__ pts) {
    int p = blockIdx.x;
    int t = threadIdx.x;  // 128 = DIM
    float v = pts[p * DIM + t];
    g_pts[p * DIM + t] = __float2half(v);
    float s = v * v;
#pragma unroll
    for (int o = 16; o > 0; o >>= 1) s += __shfl_xor_sync(0xffffffffu, s, o);
    __shared__ float ws[4];
    if ((t & 31) == 0) ws[t >> 5] = s;
    __syncthreads();
    if (t == 0) g_pn[p] = __float2half(ws[0] + ws[1] + ws[2] + ws[3]);
}

// Init: min keys to +inf key
__global__ void distnet_init() {
    g_min[blockIdx.x * 256 + threadIdx.x] = 0xFFFFFFFFu;
}

// Epilogue: decode min, add ||x||^2, sigmoid
__global__ void distnet_epi(const float* __restrict__ beta_raw,
                            float* __restrict__ out) {
    int i = blockIdx.x * 256 + threadIdx.x;
    float brv  = beta_raw[0];
    float beta = fmaxf(brv, 0.f) + log1pf(__expf(-fabsf(brv)));  // softplus
    float mn = funkey(g_min[i]);
    float md = fmaxf(g_xn[i] + mn, 0.f);
    float arg = (md - beta * LOG1000F) / beta;
    out[i] = 1.f / (1.f + __expf(-arg));
}

// ---------------------------------------------------------------------------
// Pair-scope async copy of one 32-point sub-chunk (8KB B + 64B pn).
// base = first point index of this pair's 256-point span.
__device__ __forceinline__ void issue_sub(uint32_t dst, int base, int sub, int tp) {
    const char* src = (const char*)g_pts + ((size_t)base + sub * SUBPTS) * 256;
#pragma unroll
    for (int u = 0; u < 8; u++) {
        int i = tp + u * 64;             // 0..511 16B units
        int n = i >> 4, c = i & 15;
        cp_async16(dst + n * 256 + ((c ^ (n & 7)) * 16), src + i * 16);
    }
    if (tp < 4)
        cp_async16(dst + BUFBYTES + tp * 16,
                   (const char*)g_pn + ((size_t)base + sub * SUBPTS) * 2 + tp * 16);
    asm volatile("cp.async.commit_group;" ::: "memory");
}

// ---------------------------------------------------------------------------
__global__ void __launch_bounds__(256, 2)
distnet_main(const float* __restrict__ x) {
    extern __shared__ char smem[];
    const uint32_t sb = smem_u32(smem);
    const int tid   = threadIdx.x;
    const int lane  = tid & 31;
    const int wid   = tid >> 5;        // 0..7
    const int mhalf = wid & 1;         // m32 half of the 64-row tile
    const int pair  = wid >> 1;        // 0..3
    const int tp    = tid & 63;        // thread index within pair
    const int nblk  = blockIdx.x & 1;            // which 1024-pt half
    const int row0  = (blockIdx.x >> 1) * MTILE; // row tile
    const int pbase = nblk * 1024 + pair * 256;  // this pair's point span

    const uint32_t buf0 = sb + OFF_B + pair * PAIRBYTES;
    const uint32_t buf1 = buf0 + BUFSTRIDE;

    issue_sub(buf0, pbase, 0, tp);     // prefetch sub-chunk 0

    // ---- X tile: 64 rows x 256B fp16, 4 threads per row + ||x||^2
    {
        int sub = tid & 3;
        int r   = tid >> 2;            // 0..63
        const float4* src = (const float4*)(x + (size_t)(row0 + r) * DIM);
        float s = 0.f;
#pragma unroll
        for (int j = 0; j < 4; j++) {
            int c = j * 4 + sub;       // 16B fp16 unit
            float4 v0 = src[c * 2], v1 = src[c * 2 + 1];
            s += v0.x * v0.x + v0.y * v0.y + v0.z * v0.z + v0.w * v0.w;
            s += v1.x * v1.x + v1.y * v1.y + v1.z * v1.z + v1.w * v1.w;
            __half2 p0 = __floats2half2_rn(v0.x, v0.y);
            __half2 p1 = __floats2half2_rn(v0.z, v0.w);
            __half2 p2 = __floats2half2_rn(v1.x, v1.y);
            __half2 p3 = __floats2half2_rn(v1.z, v1.w);
            uint4 pk;
            pk.x = *(uint32_t*)&p0; pk.y = *(uint32_t*)&p1;
            pk.z = *(uint32_t*)&p2; pk.w = *(uint32_t*)&p3;
            *(uint4*)(smem + OFF_X + r * 256 + ((c ^ (r & 7)) * 16)) = pk;
        }
        s += __shfl_xor_sync(0xffffffffu, s, 1);
        s += __shfl_xor_sync(0xffffffffu, s, 2);
        if (sub == 0 && nblk == 0) g_xn[row0 + r] = s;  // one CTA per tile writes
    }
    __syncthreads();

    // ---- A fragments: warp owns rows mhalf*32..+31; load once
    uint32_t afr[2][8][4];
    {
        int ar = lane & 15, ah = lane >> 4;
#pragma unroll
        for (int mt = 0; mt < 2; mt++) {
            int r = mhalf * 32 + mt * 16 + ar;
#pragma unroll
            for (int k = 0; k < 8; k++) {
                uint32_t addr = sb + OFF_X + r * 256 + (((2 * k + ah) ^ (r & 7)) * 16);
                LDMATRIX_X4(afr[mt][k], addr);
            }
        }
    }

    const int q  = lane & 3;   // col pair within n8
    const int rp = lane >> 2;  // row within 8
    const uint32_t br_ = lane & 7, bh = lane >> 3;  // B ldmatrix lane mapping
    const int barid = pair + 1;

    const __half2 mtwo = __float2half2_rn(-2.0f);
    const __half2 biginit = __float2half2_rn(60000.0f);
    __half2 rmin2[4] = {biginit, biginit, biginit, biginit};

    // ---- mainloop: pair-private two-stage pipeline over 8 sub-chunks
#pragma unroll 1
    for (int i = 0; i < NSUB; i++) {
        uint32_t buf = (i & 1) ? buf1 : buf0;
        asm volatile("cp.async.wait_group 0;" ::: "memory");
        asm volatile("bar.sync %0, 64;" :: "r"(barid) : "memory");
        if (i + 1 < NSUB)
            issue_sub((i & 1) ? buf0 : buf1, pbase, i + 1, tp);

        const __half2* pnb = (const __half2*)(smem + (buf - sb) + BUFBYTES);
        const uint32_t bl = buf + br_ * 256;
#pragma unroll
        for (int g = 0; g < 4; g++) {   // 4 n8-groups of this sub-chunk
            uint32_t acc[4] = {0u, 0u, 0u, 0u};
#pragma unroll
            for (int kk = 0; kk < 4; kk++) {      // pairs of k16 steps
                uint32_t bfr[4];
                uint32_t addr = bl + g * 2048 + (((4 * kk + bh) ^ br_) * 16);
                LDMATRIX_X4(bfr, addr);
                MMA16816H(acc + 0, afr[0][2 * kk],     bfr[0], bfr[1]);
                MMA16816H(acc + 2, afr[1][2 * kk],     bfr[0], bfr[1]);
                MMA16816H(acc + 0, afr[0][2 * kk + 1], bfr[2], bfr[3]);
                MMA16816H(acc + 2, afr[1][2 * kk + 1], bfr[2], bfr[3]);
            }
            __half2 pp = pnb[g * 4 + q];
            rmin2[0] = __hmin2(rmin2[0], __hfma2(mtwo, *(__half2*)&acc[0], pp));
            rmin2[1] = __hmin2(rmin2[1], __hfma2(mtwo, *(__half2*)&acc[1], pp));
            rmin2[2] = __hmin2(rmin2[2], __hfma2(mtwo, *(__half2*)&acc[2], pp));
            rmin2[3] = __hmin2(rmin2[3], __hfma2(mtwo, *(__half2*)&acc[3], pp));
        }
    }

    // ---- reduce across the quad (4 col-pairs = 8 cols) within each warp
    float rmin[4];
#pragma unroll
    for (int i = 0; i < 4; i++) {
        uint32_t v = *(uint32_t*)&rmin2[i];
        uint32_t v1 = __shfl_xor_sync(0xffffffffu, v, 1);
        __half2 h = __hmin2(*(__half2*)&v, *(__half2*)&v1);
        uint32_t hv = *(uint32_t*)&h;
        uint32_t v2 = __shfl_xor_sync(0xffffffffu, hv, 2);
        h = __hmin2(h, *(__half2*)&v2);
        rmin[i] = fminf(__low2float(h), __high2float(h));
    }

    // ---- direct global combine: order-preserving uint atomicMin per row
    if (q == 0) {
#pragma unroll
        for (int i = 0; i < 4; i++) {
            int rl = mhalf * 32 + i * 8 + rp;
            atomicMin(&g_min[row0 + rl], fkey(rmin[i]));
        }
    }
}

// ---------------------------------------------------------------------------
extern "C" void kernel_launch(void* const* d_in, const int* in_sizes, int n_in,
                              void* d_out, int out_size) {
    const float* x    = (const float*)d_in[0];   // [65536,128]
    const float* pts  = (const float*)d_in[1];   // [2048,128]
    const float* braw = (const float*)d_in[2];   // [1]
    float* out = (float*)d_out;                  // [65536]

    cudaFuncSetAttribute(distnet_main, cudaFuncAttributeMaxDynamicSharedMemorySize,
                         SMEM_BYTES);

    distnet_prep<<<NPTS, DIM>>>(pts);
    distnet_init<<<NROWS / 256, 256>>>();
    distnet_main<<<(NROWS / MTILE) * 2, 256, SMEM_BYTES>>>(x);
    distnet_epi<<<NROWS / 256, 256>>>(braw, out);
}